// round 8
// baseline (speedup 1.0000x reference)
#include <cuda_runtime.h>
#include <math.h>

// ---- problem constants ----
#define NFFT      512
#define HOP       256
#define NBIN      19      // rfft bins 13..31  (400 <= f < 1000 Hz, df = 31.25)
#define BIN0      13
#define NANG      18001
#define MICS      4
#define NFRM      4       // EST_NUM frames, t = 120..123
#define SAMPLE_OFF 30464  // first sample used = 119*256
#define NTCK      (NFRM * MICS * NBIN)   // 304 (t,c,k) tuples

#define NBLK      141
#define NTHR      128

// cross-block mailboxes
__device__ float2 gX[NTCK];        // DFT results
__device__ float  gQ[NBIN * 8];    // per-bin projector coefficients
__device__ unsigned int g_cnt;     // DFT warps completed
__device__ unsigned int g_flag;    // Q ready

__global__ void k_reset() { g_cnt = 0u; g_flag = 0u; }

// one complex Jacobi rotation with COMPILE-TIME (p,q) — keeps arrays in registers
#define ROT(p, q) do {                                                         \
    float gr = Ar[p][q], gi = Ai[p][q];                                        \
    float g2 = fmaf(gr, gr, gi * gi);                                          \
    if (g2 >= thr) {                                                           \
        float inv_g = rsqrtf(g2);                                              \
        float er = gr * inv_g, ei = gi * inv_g;                                \
        float tau = (Ar[q][q] - Ar[p][p]) * (0.5f * inv_g);                    \
        float t2  = fmaf(tau, tau, 1.f);                                       \
        float root = t2 * rsqrtf(t2);                                          \
        float tt = __fdividef((tau >= 0.f) ? -1.f : 1.f, fabsf(tau) + root);   \
        float cc = rsqrtf(fmaf(tt, tt, 1.f));                                  \
        float ss = tt * cc;                                                    \
        float se_r = ss * er, se_i = ss * ei;                                  \
        float ce_r = cc * er, ce_i = cc * ei;                                  \
        _Pragma("unroll")                                                      \
        for (int i = 0; i < 4; i++) {            /* A <- A R */                \
            float pr = Ar[i][p], pi = Ai[i][p];                                \
            float qr = Ar[i][q], qi = Ai[i][q];                                \
            Ar[i][p] =  pr*cc + qr*se_r + qi*se_i;                             \
            Ai[i][p] =  pi*cc - qr*se_i + qi*se_r;                             \
            Ar[i][q] = -pr*ss + qr*ce_r + qi*ce_i;                             \
            Ai[i][q] = -pi*ss - qr*ce_i + qi*ce_r;                             \
        }                                                                      \
        _Pragma("unroll")                                                      \
        for (int j = 0; j < 4; j++) {            /* A <- R^H A */              \
            float pr = Ar[p][j], pi = Ai[p][j];                                \
            float qr = Ar[q][j], qi = Ai[q][j];                                \
            Ar[p][j] =  cc*pr + se_r*qr - se_i*qi;                             \
            Ai[p][j] =  cc*pi + se_r*qi + se_i*qr;                             \
            Ar[q][j] = -ss*pr + ce_r*qr - ce_i*qi;                             \
            Ai[q][j] = -ss*pi + ce_r*qi + ce_i*qr;                             \
        }                                                                      \
        _Pragma("unroll")                                                      \
        for (int i = 0; i < 4; i++) {            /* V <- V R */                \
            float pr = Vr[i][p], pi = Vi[i][p];                                \
            float qr = Vr[i][q], qi = Vi[i][q];                                \
            Vr[i][p] =  pr*cc + qr*se_r + qi*se_i;                             \
            Vi[i][p] =  pi*cc - qr*se_i + qi*se_r;                             \
            Vr[i][q] = -pr*ss + qr*ce_r + qi*ce_i;                             \
            Vi[i][q] = -pi*ss - qr*ce_i + qi*ce_r;                             \
        }                                                                      \
    }                                                                          \
} while (0)

// ============================================================
// Single persistent kernel: 141 blocks x 128 threads, all resident.
//  phase 1: 304 warps do the windowed DFT -> gX, count up
//  phase 2: block 0 / warp 0 spins to 304, runs 19 Jacobi eigens
//           (all-register), publishes gQ, sets flag
//  phase 3: all blocks spin on flag, evaluate MUSIC spectrum
// ============================================================
__global__ void __launch_bounds__(NTHR, 1) k_music(const float* __restrict__ x,
                                                   float* __restrict__ out)
{
    __shared__ float sQ[NBIN * 8];
    const int tid = threadIdx.x;

    // ---------- phase 1: DFT (one warp per (t,c,bin) tuple) ----------
    const int gw = blockIdx.x * (NTHR / 32) + (tid >> 5);
    const int l  = tid & 31;
    if (gw < NTCK) {
        const int t   = gw / (MICS * NBIN);
        const int rem = gw % (MICS * NBIN);
        const int c   = rem / NBIN;
        const int bin = (rem % NBIN) + BIN0;

        const float ANG = -0.012271846303085130f;              // -2*pi/512
        float c1, s1, cs, ss;
        __sincosf((float)((bin * l)  & 511) * ANG, &s1, &c1);
        __sincosf((float)((bin * 32) & 511) * ANG, &ss, &cs);

        const float* px = x + ((size_t)SAMPLE_OFF + (size_t)t * HOP) * MICS + c;

        float re = 0.f, im = 0.f;
        #pragma unroll
        for (int j = 0; j < 16; j++) {
            int n = l + 32 * j;
            float v = px[n * MICS] * __sinf((float)n * (float)(M_PI / 512.0));
            re = fmaf(v, c1, re);
            im = fmaf(v, s1, im);
            float cn = fmaf(c1, cs, -s1 * ss);
            float sn = fmaf(s1, cs,  c1 * ss);
            c1 = cn; s1 = sn;
        }
        #pragma unroll
        for (int off = 16; off; off >>= 1) {
            re += __shfl_down_sync(0xffffffffu, re, off);
            im += __shfl_down_sync(0xffffffffu, im, off);
        }
        if (l == 0) {
            gX[gw] = make_float2(re, im);
            __threadfence();
            atomicAdd(&g_cnt, 1u);
        }
    }

    // ---------- phase 2: eigen (block 0, warp 0) ----------
    if (blockIdx.x == 0 && tid < 32) {
        if (tid == 0) {
            while (atomicAdd(&g_cnt, 0u) < (unsigned)NTCK) { }
        }
        __syncwarp();
        __threadfence();   // acquire: gX stores visible

        if (tid < NBIN) {
            const int f = tid;
            float Ar[4][4], Ai[4][4], Vr[4][4], Vi[4][4];

            // A[c][d] = (1/4) sum_t X[t][c] conj(X[t][d])
            #pragma unroll
            for (int c = 0; c < 4; c++)
                #pragma unroll
                for (int d = 0; d <= c; d++) {
                    float sr = 0.f, si = 0.f;
                    #pragma unroll
                    for (int t = 0; t < NFRM; t++) {
                        float2 a = __ldcg(&gX[(t * MICS + c) * NBIN + f]);
                        float2 b = __ldcg(&gX[(t * MICS + d) * NBIN + f]);
                        sr = fmaf(a.x, b.x, fmaf(a.y, b.y, sr));
                        si = fmaf(a.y, b.x, fmaf(-a.x, b.y, si));
                    }
                    Ar[c][d] = 0.25f * sr;  Ai[c][d] = 0.25f * si;
                    Ar[d][c] = 0.25f * sr;  Ai[d][c] = -0.25f * si;
                }
            #pragma unroll
            for (int c = 0; c < 4; c++) {
                Ai[c][c] = 0.f;
                #pragma unroll
                for (int d = 0; d < 4; d++) { Vr[c][d] = (c == d) ? 1.f : 0.f; Vi[c][d] = 0.f; }
            }

            float trace = Ar[0][0] + Ar[1][1] + Ar[2][2] + Ar[3][3];
            float thr   = trace * trace * 1e-14f + 1e-30f;

            for (int sweep = 0; sweep < 5; sweep++) {
                ROT(0,1); ROT(2,3);   // independent pairs -> ILP
                ROT(0,2); ROT(1,3);
                ROT(0,3); ROT(1,2);
            }

            // rank-based noise-subspace mask (no dynamic indexing!)
            float ev0 = Ar[0][0], ev1 = Ar[1][1], ev2 = Ar[2][2], ev3 = Ar[3][3];
            int r0 = (ev1 <  ev0) + (ev2 <  ev0) + (ev3 <  ev0);
            int r1 = (ev0 <= ev1) + (ev2 <  ev1) + (ev3 <  ev1);
            int r2 = (ev0 <= ev2) + (ev1 <= ev2) + (ev3 <  ev2);
            int r3 = (ev0 <= ev3) + (ev1 <= ev3) + (ev2 <= ev3);
            float w[4];
            w[0] = (r0 < 2) ? 1.f : 0.f;
            w[1] = (r1 < 2) ? 1.f : 0.f;
            w[2] = (r2 < 2) ? 1.f : 0.f;
            w[3] = (r3 < 2) ? 1.f : 0.f;

            // P_{cd} = sum_j w_j v_cj conj(v_dj)   (j unrolled -> registers)
            float Pd = 0.f;
            #pragma unroll
            for (int j = 0; j < 4; j++) {
                float s = 0.f;
                #pragma unroll
                for (int c = 0; c < 4; c++)
                    s = fmaf(Vr[c][j], Vr[c][j], fmaf(Vi[c][j], Vi[c][j], s));
                Pd = fmaf(w[j], s, Pd);
            }
            #define PCD(c, d, PR, PI)                                          \
                float PR = 0.f, PI = 0.f;                                      \
                _Pragma("unroll")                                              \
                for (int j = 0; j < 4; j++) {                                  \
                    float pr = fmaf(Vr[c][j], Vr[d][j], Vi[c][j] * Vi[d][j]);  \
                    float pi = fmaf(Vi[c][j], Vr[d][j], -Vr[c][j] * Vi[d][j]); \
                    PR = fmaf(w[j], pr, PR);                                   \
                    PI = fmaf(w[j], pi, PI);                                   \
                }
            PCD(1,0, Pr10, Pi10) PCD(2,1, Pr21, Pi21) PCD(3,2, Pr32, Pi32)
            PCD(2,0, Pr20, Pi20) PCD(3,1, Pr31, Pi31) PCD(3,0, Pr30, Pi30)
            #undef PCD

            float* qo = &gQ[f * 8];
            qo[0] = Pd;
            qo[1] = Pr10 + Pr21 + Pr32;
            qo[2] = Pi10 + Pi21 + Pi32;
            qo[3] = Pr20 + Pr31;
            qo[4] = Pi20 + Pi31;
            qo[5] = Pr30;
            qo[6] = Pi30;
            qo[7] = 0.f;
        }
        __syncwarp();
        if (tid == 0) {
            __threadfence();
            atomicExch(&g_flag, 1u);
        }
    }

    // ---------- phase 3: spectrum ----------
    if (tid == 0) {
        while (atomicAdd(&g_flag, 0u) == 0u) { }
    }
    __syncthreads();
    __threadfence();
    for (int i = tid; i < NBIN * 8; i += NTHR) sQ[i] = __ldcg(&gQ[i]);
    __syncthreads();

    int a = blockIdx.x * NTHR + tid;
    if (a >= NANG) return;

    float th = (-90.0f + 0.01f * (float)a) * 0.017453292519943295f;
    float st = __sinf(th);
    float base = (float)(2.0 * M_PI * 0.1 / 343.0) * st;

    float dphi = base * 31.25f;
    float phi0 = dphi * (float)BIN0;
    float s1, c1, sd, cd;
    __sincosf(phi0, &s1, &c1);
    __sincosf(dphi, &sd, &cd);

    float acc = 0.0f;
    #pragma unroll
    for (int k = 0; k < NBIN; k++) {
        float c2 = fmaf(c1, c1, -s1*s1);
        float s2 = 2.0f * c1 * s1;
        float c3 = fmaf(c2, c1, -s2*s1);
        float s3 = fmaf(s2, c1,  c2*s1);
        const float* q = &sQ[k * 8];
        float denom = fmaf(2.0f,
              fmaf(q[1], c1, fmaf(q[2], s1,
              fmaf(q[3], c2, fmaf(q[4], s2,
              fmaf(q[5], c3,       q[6]*s3))))),
              q[0]) + 1e-8f;
        acc += __fdividef(1.0f, denom);
        float c1n = fmaf(c1, cd, -s1*sd);
        float s1n = fmaf(s1, cd,  c1*sd);
        c1 = c1n; s1 = s1n;
    }
    out[a] = acc * (1.0f / 19.0f);
}

extern "C" void kernel_launch(void* const* d_in, const int* in_sizes, int n_in,
                              void* d_out, int out_size)
{
    const float* x = (const float*)d_in[0];
    float* out = (float*)d_out;
    k_reset<<<1, 1>>>();
    k_music<<<NBLK, NTHR>>>(x, out);
}